// round 10
// baseline (speedup 1.0000x reference)
#include <cuda_runtime.h>
#include <cuda_bf16.h>
#include <math.h>

// Problem constants
#define BATCH   2
#define SEQ     2048
#define DMODEL  1024
#define NHEAD   16
#define HD      64
#define NB      32          // SEQ / 64 query blocks
#define BS      64          // block size
#define MTOT    (BATCH*SEQ) // 4096
#define SCALE   0.125f      // 1/sqrt(64)
#define THRESH  0.99f

// Scratch (device globals: allocation-free)
__device__ float g_q[MTOT * DMODEL];
__device__ float g_k[MTOT * DMODEL];
__device__ float g_v[MTOT * DMODEL];
__device__ float g_ao[MTOT * DMODEL];
__device__ int   g_keep[BATCH * NB];

// ---------------------------------------------------------------------------
// keep mask: keep[b*NB+qb] = max |G[b, qb*64 .. qb*64+63]| >= 0.99
// ---------------------------------------------------------------------------
__global__ void keep_kernel(const float* __restrict__ G, int* __restrict__ keep) {
    int idx = blockIdx.x;                 // b*NB + qb  (G offset works out to idx*64)
    float v = fabsf(G[idx * 64 + threadIdx.x]);
    #pragma unroll
    for (int o = 16; o > 0; o >>= 1)
        v = fmaxf(v, __shfl_xor_sync(0xFFFFFFFFu, v, o));
    __shared__ float sm[2];
    if ((threadIdx.x & 31) == 0) sm[threadIdx.x >> 5] = v;
    __syncthreads();
    if (threadIdx.x == 0)
        keep[idx] = (fmaxf(sm[0], sm[1]) >= THRESH) ? 1 : 0;
}

// ---------------------------------------------------------------------------
// SGEMM: C[M,N] = A[M,K] @ B[K,N] + bias[N]   (fp32, 128x128x16, 8x8 microtile)
// M,N,K multiples of 128/128/16. 256 threads.
// ---------------------------------------------------------------------------
__global__ __launch_bounds__(256) void sgemm_bias_kernel(
    const float* __restrict__ A, const float* __restrict__ Bm,
    const float* __restrict__ bias, float* __restrict__ C,
    int M, int N, int K)
{
    const int BK = 16;
    __shared__ float As[BK][128];   // transposed A tile: As[k][m]
    __shared__ float Bs[BK][128];   // Bs[k][n]

    int tid = threadIdx.x;
    int bx = blockIdx.x;            // N tiles
    int by = blockIdx.y;            // M tiles

    const float* Ablk = A + (size_t)by * 128 * K;
    const float* Bblk = Bm + bx * 128;

    int aRow = tid >> 2;            // 0..63
    int aCol = (tid & 3) << 2;      // 0,4,8,12
    int bRow = tid >> 5;            // 0..7
    int bCol = (tid & 31) << 2;     // 0..124

    int tx = tid & 15, ty = tid >> 4;

    float acc[8][8];
    #pragma unroll
    for (int i = 0; i < 8; i++)
        #pragma unroll
        for (int j = 0; j < 8; j++) acc[i][j] = 0.f;

    for (int k0 = 0; k0 < K; k0 += BK) {
        #pragma unroll
        for (int r = 0; r < 2; r++) {
            float4 v = *(const float4*)&Ablk[(size_t)(aRow + r*64) * K + k0 + aCol];
            As[aCol + 0][aRow + r*64] = v.x;
            As[aCol + 1][aRow + r*64] = v.y;
            As[aCol + 2][aRow + r*64] = v.z;
            As[aCol + 3][aRow + r*64] = v.w;
        }
        #pragma unroll
        for (int r = 0; r < 2; r++) {
            float4 v = *(const float4*)&Bblk[(size_t)(k0 + bRow + r*8) * N + bCol];
            *(float4*)&Bs[bRow + r*8][bCol] = v;
        }
        __syncthreads();

        #pragma unroll
        for (int k = 0; k < BK; k++) {
            float ar[8], br[8];
            *(float4*)&ar[0] = *(float4*)&As[k][ty*8];
            *(float4*)&ar[4] = *(float4*)&As[k][ty*8 + 4];
            *(float4*)&br[0] = *(float4*)&Bs[k][tx*8];
            *(float4*)&br[4] = *(float4*)&Bs[k][tx*8 + 4];
            #pragma unroll
            for (int i = 0; i < 8; i++)
                #pragma unroll
                for (int j = 0; j < 8; j++)
                    acc[i][j] = fmaf(ar[i], br[j], acc[i][j]);
        }
        __syncthreads();
    }

    int rowBase = by*128 + ty*8;
    int colBase = bx*128 + tx*8;
    float bv[8];
    *(float4*)&bv[0] = *(const float4*)&bias[colBase];
    *(float4*)&bv[4] = *(const float4*)&bias[colBase + 4];
    #pragma unroll
    for (int i = 0; i < 8; i++) {
        float4 o0, o1;
        o0.x = acc[i][0] + bv[0]; o0.y = acc[i][1] + bv[1];
        o0.z = acc[i][2] + bv[2]; o0.w = acc[i][3] + bv[3];
        o1.x = acc[i][4] + bv[4]; o1.y = acc[i][5] + bv[5];
        o1.z = acc[i][6] + bv[6]; o1.w = acc[i][7] + bv[7];
        *(float4*)&C[(size_t)(rowBase + i) * N + colBase]     = o0;
        *(float4*)&C[(size_t)(rowBase + i) * N + colBase + 4] = o1;
    }
}

// ---------------------------------------------------------------------------
// Attention: one CTA per (b, h, query-block-of-64).
// Flash-style online softmax over 32-key tiles. Skipped blocks write zeros.
// Q/K/V stored as [B*S, DMODEL]; head h occupies cols h*64..h*64+63.
// ---------------------------------------------------------------------------
#define KT 32
__global__ __launch_bounds__(256) void attn_kernel(
    const float* __restrict__ Q, const float* __restrict__ K,
    const float* __restrict__ V, const int* __restrict__ keep,
    float* __restrict__ O)
{
    int blk = blockIdx.x;                 // 0 .. B*H*NB-1
    int qb = blk % NB;
    int h  = (blk / NB) % NHEAD;
    int b  = blk / (NB * NHEAD);
    int tid = threadIdx.x;

    const int row0 = b * SEQ + qb * BS;   // first query row (global)
    const int hoff = h * HD;

    if (!keep[b * NB + qb]) {
        // zero the 64x64 output tile
        for (int i = tid; i < BS * HD; i += 256) {
            int r = i >> 6, d = i & 63;
            O[(size_t)(row0 + r) * DMODEL + hoff + d] = 0.f;
        }
        return;
    }

    __shared__ float Qs[BS][HD + 1];      // 64 x 65
    __shared__ float KVs[KT][HD + 1];     // 32 x 65 (K then reused for V)
    __shared__ float Ss[BS][KT + 1];      // 64 x 33
    __shared__ float rm[BS], rl[BS], rc[BS];

    // load Q tile (64 x 64) via float4
    for (int i = tid; i < BS * HD / 4; i += 256) {
        int r = i >> 4, c4 = (i & 15) << 2;
        float4 v = *(const float4*)&Q[(size_t)(row0 + r) * DMODEL + hoff + c4];
        Qs[r][c4 + 0] = v.x; Qs[r][c4 + 1] = v.y;
        Qs[r][c4 + 2] = v.z; Qs[r][c4 + 3] = v.w;
    }
    if (tid < BS) { rm[tid] = -1e30f; rl[tid] = 0.f; }

    int tx = tid & 15, ty = tid >> 4;
    float acc[4][4];
    #pragma unroll
    for (int i = 0; i < 4; i++)
        #pragma unroll
        for (int j = 0; j < 4; j++) acc[i][j] = 0.f;

    __syncthreads();

    for (int kt = 0; kt < SEQ / KT; kt++) {
        // load K tile (32 x 64)
        for (int i = tid; i < KT * HD / 4; i += 256) {
            int r = i >> 4, c4 = (i & 15) << 2;
            float4 v = *(const float4*)&K[(size_t)(b * SEQ + kt * KT + r) * DMODEL + hoff + c4];
            KVs[r][c4 + 0] = v.x; KVs[r][c4 + 1] = v.y;
            KVs[r][c4 + 2] = v.z; KVs[r][c4 + 3] = v.w;
        }
        __syncthreads();

        // scores: thread computes rows 4*ty..+3, key-cols 2*tx..+1
        float s[4][2];
        #pragma unroll
        for (int i = 0; i < 4; i++) { s[i][0] = 0.f; s[i][1] = 0.f; }
        #pragma unroll 16
        for (int d = 0; d < HD; d++) {
            float qv0 = Qs[4*ty + 0][d];
            float qv1 = Qs[4*ty + 1][d];
            float qv2 = Qs[4*ty + 2][d];
            float qv3 = Qs[4*ty + 3][d];
            float kv0 = KVs[2*tx + 0][d];
            float kv1 = KVs[2*tx + 1][d];
            s[0][0] = fmaf(qv0, kv0, s[0][0]); s[0][1] = fmaf(qv0, kv1, s[0][1]);
            s[1][0] = fmaf(qv1, kv0, s[1][0]); s[1][1] = fmaf(qv1, kv1, s[1][1]);
            s[2][0] = fmaf(qv2, kv0, s[2][0]); s[2][1] = fmaf(qv2, kv1, s[2][1]);
            s[3][0] = fmaf(qv3, kv0, s[3][0]); s[3][1] = fmaf(qv3, kv1, s[3][1]);
        }
        #pragma unroll
        for (int i = 0; i < 4; i++) {
            Ss[4*ty + i][2*tx + 0] = s[i][0] * SCALE;
            Ss[4*ty + i][2*tx + 1] = s[i][1] * SCALE;
        }
        __syncthreads();

        // online softmax: one thread per query row
        if (tid < BS) {
            float m_old = rm[tid];
            float mx = m_old;
            #pragma unroll
            for (int k = 0; k < KT; k++) mx = fmaxf(mx, Ss[tid][k]);
            float c = __expf(m_old - mx);
            float sum = 0.f;
            #pragma unroll
            for (int k = 0; k < KT; k++) {
                float p = __expf(Ss[tid][k] - mx);
                Ss[tid][k] = p;
                sum += p;
            }
            rl[tid] = rl[tid] * c + sum;
            rm[tid] = mx;
            rc[tid] = c;
        }
        __syncthreads();

        // load V tile (reuses KVs), rescale accumulators
        for (int i = tid; i < KT * HD / 4; i += 256) {
            int r = i >> 4, c4 = (i & 15) << 2;
            float4 v = *(const float4*)&V[(size_t)(b * SEQ + kt * KT + r) * DMODEL + hoff + c4];
            KVs[r][c4 + 0] = v.x; KVs[r][c4 + 1] = v.y;
            KVs[r][c4 + 2] = v.z; KVs[r][c4 + 3] = v.w;
        }
        float cr[4];
        #pragma unroll
        for (int i = 0; i < 4; i++) cr[i] = rc[4*ty + i];
        #pragma unroll
        for (int i = 0; i < 4; i++)
            #pragma unroll
            for (int j = 0; j < 4; j++) acc[i][j] *= cr[i];
        __syncthreads();

        // O[4ty+i][4tx+j] += sum_k P[4ty+i][k] * V[k][4tx+j]
        #pragma unroll 8
        for (int k = 0; k < KT; k++) {
            float pv0 = Ss[4*ty + 0][k];
            float pv1 = Ss[4*ty + 1][k];
            float pv2 = Ss[4*ty + 2][k];
            float pv3 = Ss[4*ty + 3][k];
            float vv0 = KVs[k][4*tx + 0];
            float vv1 = KVs[k][4*tx + 1];
            float vv2 = KVs[k][4*tx + 2];
            float vv3 = KVs[k][4*tx + 3];
            acc[0][0] = fmaf(pv0, vv0, acc[0][0]); acc[0][1] = fmaf(pv0, vv1, acc[0][1]);
            acc[0][2] = fmaf(pv0, vv2, acc[0][2]); acc[0][3] = fmaf(pv0, vv3, acc[0][3]);
            acc[1][0] = fmaf(pv1, vv0, acc[1][0]); acc[1][1] = fmaf(pv1, vv1, acc[1][1]);
            acc[1][2] = fmaf(pv1, vv2, acc[1][2]); acc[1][3] = fmaf(pv1, vv3, acc[1][3]);
            acc[2][0] = fmaf(pv2, vv0, acc[2][0]); acc[2][1] = fmaf(pv2, vv1, acc[2][1]);
            acc[2][2] = fmaf(pv2, vv2, acc[2][2]); acc[2][3] = fmaf(pv2, vv3, acc[2][3]);
            acc[3][0] = fmaf(pv3, vv0, acc[3][0]); acc[3][1] = fmaf(pv3, vv1, acc[3][1]);
            acc[3][2] = fmaf(pv3, vv2, acc[3][2]); acc[3][3] = fmaf(pv3, vv3, acc[3][3]);
        }
        __syncthreads();
    }

    // epilogue: divide by row sums, store
    #pragma unroll
    for (int i = 0; i < 4; i++) {
        float inv = 1.0f / rl[4*ty + i];
        #pragma unroll
        for (int j = 0; j < 4; j++) {
            O[(size_t)(row0 + 4*ty + i) * DMODEL + hoff + 4*tx + j] = acc[i][j] * inv;
        }
    }
}

// ---------------------------------------------------------------------------
extern "C" void kernel_launch(void* const* d_in, const int* in_sizes, int n_in,
                              void* d_out, int out_size)
{
    const float* x  = (const float*)d_in[0];
    const float* G  = (const float*)d_in[1];
    const float* Wq = (const float*)d_in[2];
    const float* bq = (const float*)d_in[3];
    const float* Wk = (const float*)d_in[4];
    const float* bk = (const float*)d_in[5];
    const float* Wv = (const float*)d_in[6];
    const float* bv = (const float*)d_in[7];
    const float* Wo = (const float*)d_in[8];
    const float* bo = (const float*)d_in[9];
    float* out = (float*)d_out;

    float *q, *k, *v, *ao;
    int* keep;
    cudaGetSymbolAddress((void**)&q,  g_q);
    cudaGetSymbolAddress((void**)&k,  g_k);
    cudaGetSymbolAddress((void**)&v,  g_v);
    cudaGetSymbolAddress((void**)&ao, g_ao);
    cudaGetSymbolAddress((void**)&keep, g_keep);

    keep_kernel<<<BATCH * NB, 64>>>(G, keep);

    dim3 gemm_grid(DMODEL / 128, MTOT / 128);   // (8, 32)
    sgemm_bias_kernel<<<gemm_grid, 256>>>(x, Wq, bq, q, MTOT, DMODEL, DMODEL);
    sgemm_bias_kernel<<<gemm_grid, 256>>>(x, Wk, bk, k, MTOT, DMODEL, DMODEL);
    sgemm_bias_kernel<<<gemm_grid, 256>>>(x, Wv, bv, v, MTOT, DMODEL, DMODEL);

    attn_kernel<<<BATCH * NHEAD * NB, 256>>>(q, k, v, keep, ao);

    sgemm_bias_kernel<<<gemm_grid, 256>>>(ao, Wo, bo, out, MTOT, DMODEL, DMODEL);
}

// round 11
// speedup vs baseline: 1.0022x; 1.0022x over previous
#include <cuda_runtime.h>
#include <cuda_bf16.h>
#include <math.h>

// Problem constants
#define BATCH   2
#define SEQ     2048
#define DMODEL  1024
#define NHEAD   16
#define HD      64
#define NB      32          // SEQ / 64 query blocks
#define BS      64          // block size
#define MTOT    (BATCH*SEQ) // 4096
#define SCALE   0.125f      // 1/sqrt(64)
#define THRESH  0.99f

// Scratch (device globals: allocation-free)
__device__ float g_q[MTOT * DMODEL];
__device__ float g_k[MTOT * DMODEL];
__device__ float g_v[MTOT * DMODEL];
__device__ float g_ao[MTOT * DMODEL];
__device__ int   g_keep[BATCH * NB];

// ---------------------------------------------------------------------------
// keep mask: keep[b*NB+qb] = max |G[b, qb*64 .. qb*64+63]| >= 0.99
// ---------------------------------------------------------------------------
__global__ void keep_kernel(const float* __restrict__ G, int* __restrict__ keep) {
    int idx = blockIdx.x;                 // b*NB + qb  (G offset works out to idx*64)
    float v = fabsf(G[idx * 64 + threadIdx.x]);
    #pragma unroll
    for (int o = 16; o > 0; o >>= 1)
        v = fmaxf(v, __shfl_xor_sync(0xFFFFFFFFu, v, o));
    __shared__ float sm[2];
    if ((threadIdx.x & 31) == 0) sm[threadIdx.x >> 5] = v;
    __syncthreads();
    if (threadIdx.x == 0)
        keep[idx] = (fmaxf(sm[0], sm[1]) >= THRESH) ? 1 : 0;
}

// ---------------------------------------------------------------------------
// SGEMM: C[M,N] = A[M,K] @ B[K,N] + bias[N]   (fp32, 128x128x16, 8x8 microtile)
// M,N,K multiples of 128/128/16. 256 threads.
// ---------------------------------------------------------------------------
__global__ __launch_bounds__(256) void sgemm_bias_kernel(
    const float* __restrict__ A, const float* __restrict__ Bm,
    const float* __restrict__ bias, float* __restrict__ C,
    int M, int N, int K)
{
    const int BK = 16;
    __shared__ float As[BK][128];   // transposed A tile: As[k][m]
    __shared__ float Bs[BK][128];   // Bs[k][n]

    int tid = threadIdx.x;
    int bx = blockIdx.x;            // N tiles
    int by = blockIdx.y;            // M tiles

    const float* Ablk = A + (size_t)by * 128 * K;
    const float* Bblk = Bm + bx * 128;

    int aRow = tid >> 2;            // 0..63
    int aCol = (tid & 3) << 2;      // 0,4,8,12
    int bRow = tid >> 5;            // 0..7
    int bCol = (tid & 31) << 2;     // 0..124

    int tx = tid & 15, ty = tid >> 4;

    float acc[8][8];
    #pragma unroll
    for (int i = 0; i < 8; i++)
        #pragma unroll
        for (int j = 0; j < 8; j++) acc[i][j] = 0.f;

    for (int k0 = 0; k0 < K; k0 += BK) {
        #pragma unroll
        for (int r = 0; r < 2; r++) {
            float4 v = *(const float4*)&Ablk[(size_t)(aRow + r*64) * K + k0 + aCol];
            As[aCol + 0][aRow + r*64] = v.x;
            As[aCol + 1][aRow + r*64] = v.y;
            As[aCol + 2][aRow + r*64] = v.z;
            As[aCol + 3][aRow + r*64] = v.w;
        }
        #pragma unroll
        for (int r = 0; r < 2; r++) {
            float4 v = *(const float4*)&Bblk[(size_t)(k0 + bRow + r*8) * N + bCol];
            *(float4*)&Bs[bRow + r*8][bCol] = v;
        }
        __syncthreads();

        #pragma unroll
        for (int k = 0; k < BK; k++) {
            float ar[8], br[8];
            *(float4*)&ar[0] = *(float4*)&As[k][ty*8];
            *(float4*)&ar[4] = *(float4*)&As[k][ty*8 + 4];
            *(float4*)&br[0] = *(float4*)&Bs[k][tx*8];
            *(float4*)&br[4] = *(float4*)&Bs[k][tx*8 + 4];
            #pragma unroll
            for (int i = 0; i < 8; i++)
                #pragma unroll
                for (int j = 0; j < 8; j++)
                    acc[i][j] = fmaf(ar[i], br[j], acc[i][j]);
        }
        __syncthreads();
    }

    int rowBase = by*128 + ty*8;
    int colBase = bx*128 + tx*8;
    float bv[8];
    *(float4*)&bv[0] = *(const float4*)&bias[colBase];
    *(float4*)&bv[4] = *(const float4*)&bias[colBase + 4];
    #pragma unroll
    for (int i = 0; i < 8; i++) {
        float4 o0, o1;
        o0.x = acc[i][0] + bv[0]; o0.y = acc[i][1] + bv[1];
        o0.z = acc[i][2] + bv[2]; o0.w = acc[i][3] + bv[3];
        o1.x = acc[i][4] + bv[4]; o1.y = acc[i][5] + bv[5];
        o1.z = acc[i][6] + bv[6]; o1.w = acc[i][7] + bv[7];
        *(float4*)&C[(size_t)(rowBase + i) * N + colBase]     = o0;
        *(float4*)&C[(size_t)(rowBase + i) * N + colBase + 4] = o1;
    }
}

// ---------------------------------------------------------------------------
// Attention: one CTA per (b, h, query-block-of-64).
// Flash-style online softmax over 32-key tiles. Skipped blocks write zeros.
// Q/K/V stored as [B*S, DMODEL]; head h occupies cols h*64..h*64+63.
// ---------------------------------------------------------------------------
#define KT 32
__global__ __launch_bounds__(256) void attn_kernel(
    const float* __restrict__ Q, const float* __restrict__ K,
    const float* __restrict__ V, const int* __restrict__ keep,
    float* __restrict__ O)
{
    int blk = blockIdx.x;                 // 0 .. B*H*NB-1
    int qb = blk % NB;
    int h  = (blk / NB) % NHEAD;
    int b  = blk / (NB * NHEAD);
    int tid = threadIdx.x;

    const int row0 = b * SEQ + qb * BS;   // first query row (global)
    const int hoff = h * HD;

    if (!keep[b * NB + qb]) {
        // zero the 64x64 output tile
        for (int i = tid; i < BS * HD; i += 256) {
            int r = i >> 6, d = i & 63;
            O[(size_t)(row0 + r) * DMODEL + hoff + d] = 0.f;
        }
        return;
    }

    __shared__ float Qs[BS][HD + 1];      // 64 x 65
    __shared__ float KVs[KT][HD + 1];     // 32 x 65 (K then reused for V)
    __shared__ float Ss[BS][KT + 1];      // 64 x 33
    __shared__ float rm[BS], rl[BS], rc[BS];

    // load Q tile (64 x 64) via float4
    for (int i = tid; i < BS * HD / 4; i += 256) {
        int r = i >> 4, c4 = (i & 15) << 2;
        float4 v = *(const float4*)&Q[(size_t)(row0 + r) * DMODEL + hoff + c4];
        Qs[r][c4 + 0] = v.x; Qs[r][c4 + 1] = v.y;
        Qs[r][c4 + 2] = v.z; Qs[r][c4 + 3] = v.w;
    }
    if (tid < BS) { rm[tid] = -1e30f; rl[tid] = 0.f; }

    int tx = tid & 15, ty = tid >> 4;
    float acc[4][4];
    #pragma unroll
    for (int i = 0; i < 4; i++)
        #pragma unroll
        for (int j = 0; j < 4; j++) acc[i][j] = 0.f;

    __syncthreads();

    for (int kt = 0; kt < SEQ / KT; kt++) {
        // load K tile (32 x 64)
        for (int i = tid; i < KT * HD / 4; i += 256) {
            int r = i >> 4, c4 = (i & 15) << 2;
            float4 v = *(const float4*)&K[(size_t)(b * SEQ + kt * KT + r) * DMODEL + hoff + c4];
            KVs[r][c4 + 0] = v.x; KVs[r][c4 + 1] = v.y;
            KVs[r][c4 + 2] = v.z; KVs[r][c4 + 3] = v.w;
        }
        __syncthreads();

        // scores: thread computes rows 4*ty..+3, key-cols 2*tx..+1
        float s[4][2];
        #pragma unroll
        for (int i = 0; i < 4; i++) { s[i][0] = 0.f; s[i][1] = 0.f; }
        #pragma unroll 16
        for (int d = 0; d < HD; d++) {
            float qv0 = Qs[4*ty + 0][d];
            float qv1 = Qs[4*ty + 1][d];
            float qv2 = Qs[4*ty + 2][d];
            float qv3 = Qs[4*ty + 3][d];
            float kv0 = KVs[2*tx + 0][d];
            float kv1 = KVs[2*tx + 1][d];
            s[0][0] = fmaf(qv0, kv0, s[0][0]); s[0][1] = fmaf(qv0, kv1, s[0][1]);
            s[1][0] = fmaf(qv1, kv0, s[1][0]); s[1][1] = fmaf(qv1, kv1, s[1][1]);
            s[2][0] = fmaf(qv2, kv0, s[2][0]); s[2][1] = fmaf(qv2, kv1, s[2][1]);
            s[3][0] = fmaf(qv3, kv0, s[3][0]); s[3][1] = fmaf(qv3, kv1, s[3][1]);
        }
        #pragma unroll
        for (int i = 0; i < 4; i++) {
            Ss[4*ty + i][2*tx + 0] = s[i][0] * SCALE;
            Ss[4*ty + i][2*tx + 1] = s[i][1] * SCALE;
        }
        __syncthreads();

        // online softmax: one thread per query row
        if (tid < BS) {
            float m_old = rm[tid];
            float mx = m_old;
            #pragma unroll
            for (int k = 0; k < KT; k++) mx = fmaxf(mx, Ss[tid][k]);
            float c = __expf(m_old - mx);
            float sum = 0.f;
            #pragma unroll
            for (int k = 0; k < KT; k++) {
                float p = __expf(Ss[tid][k] - mx);
                Ss[tid][k] = p;
                sum += p;
            }
            rl[tid] = rl[tid] * c + sum;
            rm[tid] = mx;
            rc[tid] = c;
        }
        __syncthreads();

        // load V tile (reuses KVs), rescale accumulators
        for (int i = tid; i < KT * HD / 4; i += 256) {
            int r = i >> 4, c4 = (i & 15) << 2;
            float4 v = *(const float4*)&V[(size_t)(b * SEQ + kt * KT + r) * DMODEL + hoff + c4];
            KVs[r][c4 + 0] = v.x; KVs[r][c4 + 1] = v.y;
            KVs[r][c4 + 2] = v.z; KVs[r][c4 + 3] = v.w;
        }
        float cr[4];
        #pragma unroll
        for (int i = 0; i < 4; i++) cr[i] = rc[4*ty + i];
        #pragma unroll
        for (int i = 0; i < 4; i++)
            #pragma unroll
            for (int j = 0; j < 4; j++) acc[i][j] *= cr[i];
        __syncthreads();

        // O[4ty+i][4tx+j] += sum_k P[4ty+i][k] * V[k][4tx+j]
        #pragma unroll 8
        for (int k = 0; k < KT; k++) {
            float pv0 = Ss[4*ty + 0][k];
            float pv1 = Ss[4*ty + 1][k];
            float pv2 = Ss[4*ty + 2][k];
            float pv3 = Ss[4*ty + 3][k];
            float vv0 = KVs[k][4*tx + 0];
            float vv1 = KVs[k][4*tx + 1];
            float vv2 = KVs[k][4*tx + 2];
            float vv3 = KVs[k][4*tx + 3];
            acc[0][0] = fmaf(pv0, vv0, acc[0][0]); acc[0][1] = fmaf(pv0, vv1, acc[0][1]);
            acc[0][2] = fmaf(pv0, vv2, acc[0][2]); acc[0][3] = fmaf(pv0, vv3, acc[0][3]);
            acc[1][0] = fmaf(pv1, vv0, acc[1][0]); acc[1][1] = fmaf(pv1, vv1, acc[1][1]);
            acc[1][2] = fmaf(pv1, vv2, acc[1][2]); acc[1][3] = fmaf(pv1, vv3, acc[1][3]);
            acc[2][0] = fmaf(pv2, vv0, acc[2][0]); acc[2][1] = fmaf(pv2, vv1, acc[2][1]);
            acc[2][2] = fmaf(pv2, vv2, acc[2][2]); acc[2][3] = fmaf(pv2, vv3, acc[2][3]);
            acc[3][0] = fmaf(pv3, vv0, acc[3][0]); acc[3][1] = fmaf(pv3, vv1, acc[3][1]);
            acc[3][2] = fmaf(pv3, vv2, acc[3][2]); acc[3][3] = fmaf(pv3, vv3, acc[3][3]);
        }
        __syncthreads();
    }

    // epilogue: divide by row sums, store
    #pragma unroll
    for (int i = 0; i < 4; i++) {
        float inv = 1.0f / rl[4*ty + i];
        #pragma unroll
        for (int j = 0; j < 4; j++) {
            O[(size_t)(row0 + 4*ty + i) * DMODEL + hoff + 4*tx + j] = acc[i][j] * inv;
        }
    }
}

// ---------------------------------------------------------------------------
extern "C" void kernel_launch(void* const* d_in, const int* in_sizes, int n_in,
                              void* d_out, int out_size)
{
    const float* x  = (const float*)d_in[0];
    const float* G  = (const float*)d_in[1];
    const float* Wq = (const float*)d_in[2];
    const float* bq = (const float*)d_in[3];
    const float* Wk = (const float*)d_in[4];
    const float* bk = (const float*)d_in[5];
    const float* Wv = (const float*)d_in[6];
    const float* bv = (const float*)d_in[7];
    const float* Wo = (const float*)d_in[8];
    const float* bo = (const float*)d_in[9];
    float* out = (float*)d_out;

    float *q, *k, *v, *ao;
    int* keep;
    cudaGetSymbolAddress((void**)&q,  g_q);
    cudaGetSymbolAddress((void**)&k,  g_k);
    cudaGetSymbolAddress((void**)&v,  g_v);
    cudaGetSymbolAddress((void**)&ao, g_ao);
    cudaGetSymbolAddress((void**)&keep, g_keep);

    keep_kernel<<<BATCH * NB, 64>>>(G, keep);

    dim3 gemm_grid(DMODEL / 128, MTOT / 128);   // (8, 32)
    sgemm_bias_kernel<<<gemm_grid, 256>>>(x, Wq, bq, q, MTOT, DMODEL, DMODEL);
    sgemm_bias_kernel<<<gemm_grid, 256>>>(x, Wk, bk, k, MTOT, DMODEL, DMODEL);
    sgemm_bias_kernel<<<gemm_grid, 256>>>(x, Wv, bv, v, MTOT, DMODEL, DMODEL);

    attn_kernel<<<BATCH * NHEAD * NB, 256>>>(q, k, v, keep, ao);

    sgemm_bias_kernel<<<gemm_grid, 256>>>(ao, Wo, bo, out, MTOT, DMODEL, DMODEL);
}

// round 12
// speedup vs baseline: 1.0027x; 1.0005x over previous
#include <cuda_runtime.h>
#include <cuda_bf16.h>
#include <math.h>

// Problem constants
#define BATCH   2
#define SEQ     2048
#define DMODEL  1024
#define NHEAD   16
#define HD      64
#define NB      32          // SEQ / 64 query blocks
#define BS      64          // block size
#define MTOT    (BATCH*SEQ) // 4096
#define SCALE   0.125f      // 1/sqrt(64)
#define THRESH  0.99f

// Scratch (device globals: allocation-free)
__device__ float g_q[MTOT * DMODEL];
__device__ float g_k[MTOT * DMODEL];
__device__ float g_v[MTOT * DMODEL];
__device__ float g_ao[MTOT * DMODEL];
__device__ int   g_keep[BATCH * NB];

// ---------------------------------------------------------------------------
// keep mask: keep[b*NB+qb] = max |G[b, qb*64 .. qb*64+63]| >= 0.99
// ---------------------------------------------------------------------------
__global__ void keep_kernel(const float* __restrict__ G, int* __restrict__ keep) {
    int idx = blockIdx.x;                 // b*NB + qb  (G offset works out to idx*64)
    float v = fabsf(G[idx * 64 + threadIdx.x]);
    #pragma unroll
    for (int o = 16; o > 0; o >>= 1)
        v = fmaxf(v, __shfl_xor_sync(0xFFFFFFFFu, v, o));
    __shared__ float sm[2];
    if ((threadIdx.x & 31) == 0) sm[threadIdx.x >> 5] = v;
    __syncthreads();
    if (threadIdx.x == 0)
        keep[idx] = (fmaxf(sm[0], sm[1]) >= THRESH) ? 1 : 0;
}

// ---------------------------------------------------------------------------
// SGEMM: C[M,N] = A[M,K] @ B[K,N] + bias[N]   (fp32, 128x128x16, 8x8 microtile)
// M,N,K multiples of 128/128/16. 256 threads.
// ---------------------------------------------------------------------------
__global__ __launch_bounds__(256) void sgemm_bias_kernel(
    const float* __restrict__ A, const float* __restrict__ Bm,
    const float* __restrict__ bias, float* __restrict__ C,
    int M, int N, int K)
{
    const int BK = 16;
    __shared__ float As[BK][128];   // transposed A tile: As[k][m]
    __shared__ float Bs[BK][128];   // Bs[k][n]

    int tid = threadIdx.x;
    int bx = blockIdx.x;            // N tiles
    int by = blockIdx.y;            // M tiles

    const float* Ablk = A + (size_t)by * 128 * K;
    const float* Bblk = Bm + bx * 128;

    int aRow = tid >> 2;            // 0..63
    int aCol = (tid & 3) << 2;      // 0,4,8,12
    int bRow = tid >> 5;            // 0..7
    int bCol = (tid & 31) << 2;     // 0..124

    int tx = tid & 15, ty = tid >> 4;

    float acc[8][8];
    #pragma unroll
    for (int i = 0; i < 8; i++)
        #pragma unroll
        for (int j = 0; j < 8; j++) acc[i][j] = 0.f;

    for (int k0 = 0; k0 < K; k0 += BK) {
        #pragma unroll
        for (int r = 0; r < 2; r++) {
            float4 v = *(const float4*)&Ablk[(size_t)(aRow + r*64) * K + k0 + aCol];
            As[aCol + 0][aRow + r*64] = v.x;
            As[aCol + 1][aRow + r*64] = v.y;
            As[aCol + 2][aRow + r*64] = v.z;
            As[aCol + 3][aRow + r*64] = v.w;
        }
        #pragma unroll
        for (int r = 0; r < 2; r++) {
            float4 v = *(const float4*)&Bblk[(size_t)(k0 + bRow + r*8) * N + bCol];
            *(float4*)&Bs[bRow + r*8][bCol] = v;
        }
        __syncthreads();

        #pragma unroll
        for (int k = 0; k < BK; k++) {
            float ar[8], br[8];
            *(float4*)&ar[0] = *(float4*)&As[k][ty*8];
            *(float4*)&ar[4] = *(float4*)&As[k][ty*8 + 4];
            *(float4*)&br[0] = *(float4*)&Bs[k][tx*8];
            *(float4*)&br[4] = *(float4*)&Bs[k][tx*8 + 4];
            #pragma unroll
            for (int i = 0; i < 8; i++)
                #pragma unroll
                for (int j = 0; j < 8; j++)
                    acc[i][j] = fmaf(ar[i], br[j], acc[i][j]);
        }
        __syncthreads();
    }

    int rowBase = by*128 + ty*8;
    int colBase = bx*128 + tx*8;
    float bv[8];
    *(float4*)&bv[0] = *(const float4*)&bias[colBase];
    *(float4*)&bv[4] = *(const float4*)&bias[colBase + 4];
    #pragma unroll
    for (int i = 0; i < 8; i++) {
        float4 o0, o1;
        o0.x = acc[i][0] + bv[0]; o0.y = acc[i][1] + bv[1];
        o0.z = acc[i][2] + bv[2]; o0.w = acc[i][3] + bv[3];
        o1.x = acc[i][4] + bv[4]; o1.y = acc[i][5] + bv[5];
        o1.z = acc[i][6] + bv[6]; o1.w = acc[i][7] + bv[7];
        *(float4*)&C[(size_t)(rowBase + i) * N + colBase]     = o0;
        *(float4*)&C[(size_t)(rowBase + i) * N + colBase + 4] = o1;
    }
}

// ---------------------------------------------------------------------------
// Attention: one CTA per (b, h, query-block-of-64).
// Flash-style online softmax over 32-key tiles. Skipped blocks write zeros.
// Q/K/V stored as [B*S, DMODEL]; head h occupies cols h*64..h*64+63.
// ---------------------------------------------------------------------------
#define KT 32
__global__ __launch_bounds__(256) void attn_kernel(
    const float* __restrict__ Q, const float* __restrict__ K,
    const float* __restrict__ V, const int* __restrict__ keep,
    float* __restrict__ O)
{
    int blk = blockIdx.x;                 // 0 .. B*H*NB-1
    int qb = blk % NB;
    int h  = (blk / NB) % NHEAD;
    int b  = blk / (NB * NHEAD);
    int tid = threadIdx.x;

    const int row0 = b * SEQ + qb * BS;   // first query row (global)
    const int hoff = h * HD;

    if (!keep[b * NB + qb]) {
        // zero the 64x64 output tile
        for (int i = tid; i < BS * HD; i += 256) {
            int r = i >> 6, d = i & 63;
            O[(size_t)(row0 + r) * DMODEL + hoff + d] = 0.f;
        }
        return;
    }

    __shared__ float Qs[BS][HD + 1];      // 64 x 65
    __shared__ float KVs[KT][HD + 1];     // 32 x 65 (K then reused for V)
    __shared__ float Ss[BS][KT + 1];      // 64 x 33
    __shared__ float rm[BS], rl[BS], rc[BS];

    // load Q tile (64 x 64) via float4
    for (int i = tid; i < BS * HD / 4; i += 256) {
        int r = i >> 4, c4 = (i & 15) << 2;
        float4 v = *(const float4*)&Q[(size_t)(row0 + r) * DMODEL + hoff + c4];
        Qs[r][c4 + 0] = v.x; Qs[r][c4 + 1] = v.y;
        Qs[r][c4 + 2] = v.z; Qs[r][c4 + 3] = v.w;
    }
    if (tid < BS) { rm[tid] = -1e30f; rl[tid] = 0.f; }

    int tx = tid & 15, ty = tid >> 4;
    float acc[4][4];
    #pragma unroll
    for (int i = 0; i < 4; i++)
        #pragma unroll
        for (int j = 0; j < 4; j++) acc[i][j] = 0.f;

    __syncthreads();

    for (int kt = 0; kt < SEQ / KT; kt++) {
        // load K tile (32 x 64)
        for (int i = tid; i < KT * HD / 4; i += 256) {
            int r = i >> 4, c4 = (i & 15) << 2;
            float4 v = *(const float4*)&K[(size_t)(b * SEQ + kt * KT + r) * DMODEL + hoff + c4];
            KVs[r][c4 + 0] = v.x; KVs[r][c4 + 1] = v.y;
            KVs[r][c4 + 2] = v.z; KVs[r][c4 + 3] = v.w;
        }
        __syncthreads();

        // scores: thread computes rows 4*ty..+3, key-cols 2*tx..+1
        float s[4][2];
        #pragma unroll
        for (int i = 0; i < 4; i++) { s[i][0] = 0.f; s[i][1] = 0.f; }
        #pragma unroll 16
        for (int d = 0; d < HD; d++) {
            float qv0 = Qs[4*ty + 0][d];
            float qv1 = Qs[4*ty + 1][d];
            float qv2 = Qs[4*ty + 2][d];
            float qv3 = Qs[4*ty + 3][d];
            float kv0 = KVs[2*tx + 0][d];
            float kv1 = KVs[2*tx + 1][d];
            s[0][0] = fmaf(qv0, kv0, s[0][0]); s[0][1] = fmaf(qv0, kv1, s[0][1]);
            s[1][0] = fmaf(qv1, kv0, s[1][0]); s[1][1] = fmaf(qv1, kv1, s[1][1]);
            s[2][0] = fmaf(qv2, kv0, s[2][0]); s[2][1] = fmaf(qv2, kv1, s[2][1]);
            s[3][0] = fmaf(qv3, kv0, s[3][0]); s[3][1] = fmaf(qv3, kv1, s[3][1]);
        }
        #pragma unroll
        for (int i = 0; i < 4; i++) {
            Ss[4*ty + i][2*tx + 0] = s[i][0] * SCALE;
            Ss[4*ty + i][2*tx + 1] = s[i][1] * SCALE;
        }
        __syncthreads();

        // online softmax: one thread per query row
        if (tid < BS) {
            float m_old = rm[tid];
            float mx = m_old;
            #pragma unroll
            for (int k = 0; k < KT; k++) mx = fmaxf(mx, Ss[tid][k]);
            float c = __expf(m_old - mx);
            float sum = 0.f;
            #pragma unroll
            for (int k = 0; k < KT; k++) {
                float p = __expf(Ss[tid][k] - mx);
                Ss[tid][k] = p;
                sum += p;
            }
            rl[tid] = rl[tid] * c + sum;
            rm[tid] = mx;
            rc[tid] = c;
        }
        __syncthreads();

        // load V tile (reuses KVs), rescale accumulators
        for (int i = tid; i < KT * HD / 4; i += 256) {
            int r = i >> 4, c4 = (i & 15) << 2;
            float4 v = *(const float4*)&V[(size_t)(b * SEQ + kt * KT + r) * DMODEL + hoff + c4];
            KVs[r][c4 + 0] = v.x; KVs[r][c4 + 1] = v.y;
            KVs[r][c4 + 2] = v.z; KVs[r][c4 + 3] = v.w;
        }
        float cr[4];
        #pragma unroll
        for (int i = 0; i < 4; i++) cr[i] = rc[4*ty + i];
        #pragma unroll
        for (int i = 0; i < 4; i++)
            #pragma unroll
            for (int j = 0; j < 4; j++) acc[i][j] *= cr[i];
        __syncthreads();

        // O[4ty+i][4tx+j] += sum_k P[4ty+i][k] * V[k][4tx+j]
        #pragma unroll 8
        for (int k = 0; k < KT; k++) {
            float pv0 = Ss[4*ty + 0][k];
            float pv1 = Ss[4*ty + 1][k];
            float pv2 = Ss[4*ty + 2][k];
            float pv3 = Ss[4*ty + 3][k];
            float vv0 = KVs[k][4*tx + 0];
            float vv1 = KVs[k][4*tx + 1];
            float vv2 = KVs[k][4*tx + 2];
            float vv3 = KVs[k][4*tx + 3];
            acc[0][0] = fmaf(pv0, vv0, acc[0][0]); acc[0][1] = fmaf(pv0, vv1, acc[0][1]);
            acc[0][2] = fmaf(pv0, vv2, acc[0][2]); acc[0][3] = fmaf(pv0, vv3, acc[0][3]);
            acc[1][0] = fmaf(pv1, vv0, acc[1][0]); acc[1][1] = fmaf(pv1, vv1, acc[1][1]);
            acc[1][2] = fmaf(pv1, vv2, acc[1][2]); acc[1][3] = fmaf(pv1, vv3, acc[1][3]);
            acc[2][0] = fmaf(pv2, vv0, acc[2][0]); acc[2][1] = fmaf(pv2, vv1, acc[2][1]);
            acc[2][2] = fmaf(pv2, vv2, acc[2][2]); acc[2][3] = fmaf(pv2, vv3, acc[2][3]);
            acc[3][0] = fmaf(pv3, vv0, acc[3][0]); acc[3][1] = fmaf(pv3, vv1, acc[3][1]);
            acc[3][2] = fmaf(pv3, vv2, acc[3][2]); acc[3][3] = fmaf(pv3, vv3, acc[3][3]);
        }
        __syncthreads();
    }

    // epilogue: divide by row sums, store
    #pragma unroll
    for (int i = 0; i < 4; i++) {
        float inv = 1.0f / rl[4*ty + i];
        #pragma unroll
        for (int j = 0; j < 4; j++) {
            O[(size_t)(row0 + 4*ty + i) * DMODEL + hoff + 4*tx + j] = acc[i][j] * inv;
        }
    }
}

// ---------------------------------------------------------------------------
extern "C" void kernel_launch(void* const* d_in, const int* in_sizes, int n_in,
                              void* d_out, int out_size)
{
    const float* x  = (const float*)d_in[0];
    const float* G  = (const float*)d_in[1];
    const float* Wq = (const float*)d_in[2];
    const float* bq = (const float*)d_in[3];
    const float* Wk = (const float*)d_in[4];
    const float* bk = (const float*)d_in[5];
    const float* Wv = (const float*)d_in[6];
    const float* bv = (const float*)d_in[7];
    const float* Wo = (const float*)d_in[8];
    const float* bo = (const float*)d_in[9];
    float* out = (float*)d_out;

    float *q, *k, *v, *ao;
    int* keep;
    cudaGetSymbolAddress((void**)&q,  g_q);
    cudaGetSymbolAddress((void**)&k,  g_k);
    cudaGetSymbolAddress((void**)&v,  g_v);
    cudaGetSymbolAddress((void**)&ao, g_ao);
    cudaGetSymbolAddress((void**)&keep, g_keep);

    keep_kernel<<<BATCH * NB, 64>>>(G, keep);

    dim3 gemm_grid(DMODEL / 128, MTOT / 128);   // (8, 32)
    sgemm_bias_kernel<<<gemm_grid, 256>>>(x, Wq, bq, q, MTOT, DMODEL, DMODEL);
    sgemm_bias_kernel<<<gemm_grid, 256>>>(x, Wk, bk, k, MTOT, DMODEL, DMODEL);
    sgemm_bias_kernel<<<gemm_grid, 256>>>(x, Wv, bv, v, MTOT, DMODEL, DMODEL);

    attn_kernel<<<BATCH * NHEAD * NB, 256>>>(q, k, v, keep, ao);

    sgemm_bias_kernel<<<gemm_grid, 256>>>(ao, Wo, bo, out, MTOT, DMODEL, DMODEL);
}

// round 13
// speedup vs baseline: 1.0029x; 1.0002x over previous
#include <cuda_runtime.h>
#include <cuda_bf16.h>
#include <math.h>

// Problem constants
#define BATCH   2
#define SEQ     2048
#define DMODEL  1024
#define NHEAD   16
#define HD      64
#define NB      32          // SEQ / 64 query blocks
#define BS      64          // block size
#define MTOT    (BATCH*SEQ) // 4096
#define SCALE   0.125f      // 1/sqrt(64)
#define THRESH  0.99f

// Scratch (device globals: allocation-free)
__device__ float g_q[MTOT * DMODEL];
__device__ float g_k[MTOT * DMODEL];
__device__ float g_v[MTOT * DMODEL];
__device__ float g_ao[MTOT * DMODEL];
__device__ int   g_keep[BATCH * NB];

// ---------------------------------------------------------------------------
// keep mask: keep[b*NB+qb] = max |G[b, qb*64 .. qb*64+63]| >= 0.99
// ---------------------------------------------------------------------------
__global__ void keep_kernel(const float* __restrict__ G, int* __restrict__ keep) {
    int idx = blockIdx.x;                 // b*NB + qb  (G offset works out to idx*64)
    float v = fabsf(G[idx * 64 + threadIdx.x]);
    #pragma unroll
    for (int o = 16; o > 0; o >>= 1)
        v = fmaxf(v, __shfl_xor_sync(0xFFFFFFFFu, v, o));
    __shared__ float sm[2];
    if ((threadIdx.x & 31) == 0) sm[threadIdx.x >> 5] = v;
    __syncthreads();
    if (threadIdx.x == 0)
        keep[idx] = (fmaxf(sm[0], sm[1]) >= THRESH) ? 1 : 0;
}

// ---------------------------------------------------------------------------
// SGEMM: C[M,N] = A[M,K] @ B[K,N] + bias[N]   (fp32, 128x128x16, 8x8 microtile)
// M,N,K multiples of 128/128/16. 256 threads.
// ---------------------------------------------------------------------------
__global__ __launch_bounds__(256) void sgemm_bias_kernel(
    const float* __restrict__ A, const float* __restrict__ Bm,
    const float* __restrict__ bias, float* __restrict__ C,
    int M, int N, int K)
{
    const int BK = 16;
    __shared__ float As[BK][128];   // transposed A tile: As[k][m]
    __shared__ float Bs[BK][128];   // Bs[k][n]

    int tid = threadIdx.x;
    int bx = blockIdx.x;            // N tiles
    int by = blockIdx.y;            // M tiles

    const float* Ablk = A + (size_t)by * 128 * K;
    const float* Bblk = Bm + bx * 128;

    int aRow = tid >> 2;            // 0..63
    int aCol = (tid & 3) << 2;      // 0,4,8,12
    int bRow = tid >> 5;            // 0..7
    int bCol = (tid & 31) << 2;     // 0..124

    int tx = tid & 15, ty = tid >> 4;

    float acc[8][8];
    #pragma unroll
    for (int i = 0; i < 8; i++)
        #pragma unroll
        for (int j = 0; j < 8; j++) acc[i][j] = 0.f;

    for (int k0 = 0; k0 < K; k0 += BK) {
        #pragma unroll
        for (int r = 0; r < 2; r++) {
            float4 v = *(const float4*)&Ablk[(size_t)(aRow + r*64) * K + k0 + aCol];
            As[aCol + 0][aRow + r*64] = v.x;
            As[aCol + 1][aRow + r*64] = v.y;
            As[aCol + 2][aRow + r*64] = v.z;
            As[aCol + 3][aRow + r*64] = v.w;
        }
        #pragma unroll
        for (int r = 0; r < 2; r++) {
            float4 v = *(const float4*)&Bblk[(size_t)(k0 + bRow + r*8) * N + bCol];
            *(float4*)&Bs[bRow + r*8][bCol] = v;
        }
        __syncthreads();

        #pragma unroll
        for (int k = 0; k < BK; k++) {
            float ar[8], br[8];
            *(float4*)&ar[0] = *(float4*)&As[k][ty*8];
            *(float4*)&ar[4] = *(float4*)&As[k][ty*8 + 4];
            *(float4*)&br[0] = *(float4*)&Bs[k][tx*8];
            *(float4*)&br[4] = *(float4*)&Bs[k][tx*8 + 4];
            #pragma unroll
            for (int i = 0; i < 8; i++)
                #pragma unroll
                for (int j = 0; j < 8; j++)
                    acc[i][j] = fmaf(ar[i], br[j], acc[i][j]);
        }
        __syncthreads();
    }

    int rowBase = by*128 + ty*8;
    int colBase = bx*128 + tx*8;
    float bv[8];
    *(float4*)&bv[0] = *(const float4*)&bias[colBase];
    *(float4*)&bv[4] = *(const float4*)&bias[colBase + 4];
    #pragma unroll
    for (int i = 0; i < 8; i++) {
        float4 o0, o1;
        o0.x = acc[i][0] + bv[0]; o0.y = acc[i][1] + bv[1];
        o0.z = acc[i][2] + bv[2]; o0.w = acc[i][3] + bv[3];
        o1.x = acc[i][4] + bv[4]; o1.y = acc[i][5] + bv[5];
        o1.z = acc[i][6] + bv[6]; o1.w = acc[i][7] + bv[7];
        *(float4*)&C[(size_t)(rowBase + i) * N + colBase]     = o0;
        *(float4*)&C[(size_t)(rowBase + i) * N + colBase + 4] = o1;
    }
}

// ---------------------------------------------------------------------------
// Attention: one CTA per (b, h, query-block-of-64).
// Flash-style online softmax over 32-key tiles. Skipped blocks write zeros.
// Q/K/V stored as [B*S, DMODEL]; head h occupies cols h*64..h*64+63.
// ---------------------------------------------------------------------------
#define KT 32
__global__ __launch_bounds__(256) void attn_kernel(
    const float* __restrict__ Q, const float* __restrict__ K,
    const float* __restrict__ V, const int* __restrict__ keep,
    float* __restrict__ O)
{
    int blk = blockIdx.x;                 // 0 .. B*H*NB-1
    int qb = blk % NB;
    int h  = (blk / NB) % NHEAD;
    int b  = blk / (NB * NHEAD);
    int tid = threadIdx.x;

    const int row0 = b * SEQ + qb * BS;   // first query row (global)
    const int hoff = h * HD;

    if (!keep[b * NB + qb]) {
        // zero the 64x64 output tile
        for (int i = tid; i < BS * HD; i += 256) {
            int r = i >> 6, d = i & 63;
            O[(size_t)(row0 + r) * DMODEL + hoff + d] = 0.f;
        }
        return;
    }

    __shared__ float Qs[BS][HD + 1];      // 64 x 65
    __shared__ float KVs[KT][HD + 1];     // 32 x 65 (K then reused for V)
    __shared__ float Ss[BS][KT + 1];      // 64 x 33
    __shared__ float rm[BS], rl[BS], rc[BS];

    // load Q tile (64 x 64) via float4
    for (int i = tid; i < BS * HD / 4; i += 256) {
        int r = i >> 4, c4 = (i & 15) << 2;
        float4 v = *(const float4*)&Q[(size_t)(row0 + r) * DMODEL + hoff + c4];
        Qs[r][c4 + 0] = v.x; Qs[r][c4 + 1] = v.y;
        Qs[r][c4 + 2] = v.z; Qs[r][c4 + 3] = v.w;
    }
    if (tid < BS) { rm[tid] = -1e30f; rl[tid] = 0.f; }

    int tx = tid & 15, ty = tid >> 4;
    float acc[4][4];
    #pragma unroll
    for (int i = 0; i < 4; i++)
        #pragma unroll
        for (int j = 0; j < 4; j++) acc[i][j] = 0.f;

    __syncthreads();

    for (int kt = 0; kt < SEQ / KT; kt++) {
        // load K tile (32 x 64)
        for (int i = tid; i < KT * HD / 4; i += 256) {
            int r = i >> 4, c4 = (i & 15) << 2;
            float4 v = *(const float4*)&K[(size_t)(b * SEQ + kt * KT + r) * DMODEL + hoff + c4];
            KVs[r][c4 + 0] = v.x; KVs[r][c4 + 1] = v.y;
            KVs[r][c4 + 2] = v.z; KVs[r][c4 + 3] = v.w;
        }
        __syncthreads();

        // scores: thread computes rows 4*ty..+3, key-cols 2*tx..+1
        float s[4][2];
        #pragma unroll
        for (int i = 0; i < 4; i++) { s[i][0] = 0.f; s[i][1] = 0.f; }
        #pragma unroll 16
        for (int d = 0; d < HD; d++) {
            float qv0 = Qs[4*ty + 0][d];
            float qv1 = Qs[4*ty + 1][d];
            float qv2 = Qs[4*ty + 2][d];
            float qv3 = Qs[4*ty + 3][d];
            float kv0 = KVs[2*tx + 0][d];
            float kv1 = KVs[2*tx + 1][d];
            s[0][0] = fmaf(qv0, kv0, s[0][0]); s[0][1] = fmaf(qv0, kv1, s[0][1]);
            s[1][0] = fmaf(qv1, kv0, s[1][0]); s[1][1] = fmaf(qv1, kv1, s[1][1]);
            s[2][0] = fmaf(qv2, kv0, s[2][0]); s[2][1] = fmaf(qv2, kv1, s[2][1]);
            s[3][0] = fmaf(qv3, kv0, s[3][0]); s[3][1] = fmaf(qv3, kv1, s[3][1]);
        }
        #pragma unroll
        for (int i = 0; i < 4; i++) {
            Ss[4*ty + i][2*tx + 0] = s[i][0] * SCALE;
            Ss[4*ty + i][2*tx + 1] = s[i][1] * SCALE;
        }
        __syncthreads();

        // online softmax: one thread per query row
        if (tid < BS) {
            float m_old = rm[tid];
            float mx = m_old;
            #pragma unroll
            for (int k = 0; k < KT; k++) mx = fmaxf(mx, Ss[tid][k]);
            float c = __expf(m_old - mx);
            float sum = 0.f;
            #pragma unroll
            for (int k = 0; k < KT; k++) {
                float p = __expf(Ss[tid][k] - mx);
                Ss[tid][k] = p;
                sum += p;
            }
            rl[tid] = rl[tid] * c + sum;
            rm[tid] = mx;
            rc[tid] = c;
        }
        __syncthreads();

        // load V tile (reuses KVs), rescale accumulators
        for (int i = tid; i < KT * HD / 4; i += 256) {
            int r = i >> 4, c4 = (i & 15) << 2;
            float4 v = *(const float4*)&V[(size_t)(b * SEQ + kt * KT + r) * DMODEL + hoff + c4];
            KVs[r][c4 + 0] = v.x; KVs[r][c4 + 1] = v.y;
            KVs[r][c4 + 2] = v.z; KVs[r][c4 + 3] = v.w;
        }
        float cr[4];
        #pragma unroll
        for (int i = 0; i < 4; i++) cr[i] = rc[4*ty + i];
        #pragma unroll
        for (int i = 0; i < 4; i++)
            #pragma unroll
            for (int j = 0; j < 4; j++) acc[i][j] *= cr[i];
        __syncthreads();

        // O[4ty+i][4tx+j] += sum_k P[4ty+i][k] * V[k][4tx+j]
        #pragma unroll 8
        for (int k = 0; k < KT; k++) {
            float pv0 = Ss[4*ty + 0][k];
            float pv1 = Ss[4*ty + 1][k];
            float pv2 = Ss[4*ty + 2][k];
            float pv3 = Ss[4*ty + 3][k];
            float vv0 = KVs[k][4*tx + 0];
            float vv1 = KVs[k][4*tx + 1];
            float vv2 = KVs[k][4*tx + 2];
            float vv3 = KVs[k][4*tx + 3];
            acc[0][0] = fmaf(pv0, vv0, acc[0][0]); acc[0][1] = fmaf(pv0, vv1, acc[0][1]);
            acc[0][2] = fmaf(pv0, vv2, acc[0][2]); acc[0][3] = fmaf(pv0, vv3, acc[0][3]);
            acc[1][0] = fmaf(pv1, vv0, acc[1][0]); acc[1][1] = fmaf(pv1, vv1, acc[1][1]);
            acc[1][2] = fmaf(pv1, vv2, acc[1][2]); acc[1][3] = fmaf(pv1, vv3, acc[1][3]);
            acc[2][0] = fmaf(pv2, vv0, acc[2][0]); acc[2][1] = fmaf(pv2, vv1, acc[2][1]);
            acc[2][2] = fmaf(pv2, vv2, acc[2][2]); acc[2][3] = fmaf(pv2, vv3, acc[2][3]);
            acc[3][0] = fmaf(pv3, vv0, acc[3][0]); acc[3][1] = fmaf(pv3, vv1, acc[3][1]);
            acc[3][2] = fmaf(pv3, vv2, acc[3][2]); acc[3][3] = fmaf(pv3, vv3, acc[3][3]);
        }
        __syncthreads();
    }

    // epilogue: divide by row sums, store
    #pragma unroll
    for (int i = 0; i < 4; i++) {
        float inv = 1.0f / rl[4*ty + i];
        #pragma unroll
        for (int j = 0; j < 4; j++) {
            O[(size_t)(row0 + 4*ty + i) * DMODEL + hoff + 4*tx + j] = acc[i][j] * inv;
        }
    }
}

// ---------------------------------------------------------------------------
extern "C" void kernel_launch(void* const* d_in, const int* in_sizes, int n_in,
                              void* d_out, int out_size)
{
    const float* x  = (const float*)d_in[0];
    const float* G  = (const float*)d_in[1];
    const float* Wq = (const float*)d_in[2];
    const float* bq = (const float*)d_in[3];
    const float* Wk = (const float*)d_in[4];
    const float* bk = (const float*)d_in[5];
    const float* Wv = (const float*)d_in[6];
    const float* bv = (const float*)d_in[7];
    const float* Wo = (const float*)d_in[8];
    const float* bo = (const float*)d_in[9];
    float* out = (float*)d_out;

    float *q, *k, *v, *ao;
    int* keep;
    cudaGetSymbolAddress((void**)&q,  g_q);
    cudaGetSymbolAddress((void**)&k,  g_k);
    cudaGetSymbolAddress((void**)&v,  g_v);
    cudaGetSymbolAddress((void**)&ao, g_ao);
    cudaGetSymbolAddress((void**)&keep, g_keep);

    keep_kernel<<<BATCH * NB, 64>>>(G, keep);

    dim3 gemm_grid(DMODEL / 128, MTOT / 128);   // (8, 32)
    sgemm_bias_kernel<<<gemm_grid, 256>>>(x, Wq, bq, q, MTOT, DMODEL, DMODEL);
    sgemm_bias_kernel<<<gemm_grid, 256>>>(x, Wk, bk, k, MTOT, DMODEL, DMODEL);
    sgemm_bias_kernel<<<gemm_grid, 256>>>(x, Wv, bv, v, MTOT, DMODEL, DMODEL);

    attn_kernel<<<BATCH * NHEAD * NB, 256>>>(q, k, v, keep, ao);

    sgemm_bias_kernel<<<gemm_grid, 256>>>(ao, Wo, bo, out, MTOT, DMODEL, DMODEL);
}

// round 14
// speedup vs baseline: 1.0040x; 1.0011x over previous
#include <cuda_runtime.h>
#include <cuda_bf16.h>
#include <math.h>

// Problem constants
#define BATCH   2
#define SEQ     2048
#define DMODEL  1024
#define NHEAD   16
#define HD      64
#define NB      32          // SEQ / 64 query blocks
#define BS      64          // block size
#define MTOT    (BATCH*SEQ) // 4096
#define SCALE   0.125f      // 1/sqrt(64)
#define THRESH  0.99f

// Scratch (device globals: allocation-free)
__device__ float g_q[MTOT * DMODEL];
__device__ float g_k[MTOT * DMODEL];
__device__ float g_v[MTOT * DMODEL];
__device__ float g_ao[MTOT * DMODEL];
__device__ int   g_keep[BATCH * NB];

// ---------------------------------------------------------------------------
// keep mask: keep[b*NB+qb] = max |G[b, qb*64 .. qb*64+63]| >= 0.99
// ---------------------------------------------------------------------------
__global__ void keep_kernel(const float* __restrict__ G, int* __restrict__ keep) {
    int idx = blockIdx.x;                 // b*NB + qb  (G offset works out to idx*64)
    float v = fabsf(G[idx * 64 + threadIdx.x]);
    #pragma unroll
    for (int o = 16; o > 0; o >>= 1)
        v = fmaxf(v, __shfl_xor_sync(0xFFFFFFFFu, v, o));
    __shared__ float sm[2];
    if ((threadIdx.x & 31) == 0) sm[threadIdx.x >> 5] = v;
    __syncthreads();
    if (threadIdx.x == 0)
        keep[idx] = (fmaxf(sm[0], sm[1]) >= THRESH) ? 1 : 0;
}

// ---------------------------------------------------------------------------
// SGEMM: C[M,N] = A[M,K] @ B[K,N] + bias[N]   (fp32, 128x128x16, 8x8 microtile)
// M,N,K multiples of 128/128/16. 256 threads.
// ---------------------------------------------------------------------------
__global__ __launch_bounds__(256) void sgemm_bias_kernel(
    const float* __restrict__ A, const float* __restrict__ Bm,
    const float* __restrict__ bias, float* __restrict__ C,
    int M, int N, int K)
{
    const int BK = 16;
    __shared__ float As[BK][128];   // transposed A tile: As[k][m]
    __shared__ float Bs[BK][128];   // Bs[k][n]

    int tid = threadIdx.x;
    int bx = blockIdx.x;            // N tiles
    int by = blockIdx.y;            // M tiles

    const float* Ablk = A + (size_t)by * 128 * K;
    const float* Bblk = Bm + bx * 128;

    int aRow = tid >> 2;            // 0..63
    int aCol = (tid & 3) << 2;      // 0,4,8,12
    int bRow = tid >> 5;            // 0..7
    int bCol = (tid & 31) << 2;     // 0..124

    int tx = tid & 15, ty = tid >> 4;

    float acc[8][8];
    #pragma unroll
    for (int i = 0; i < 8; i++)
        #pragma unroll
        for (int j = 0; j < 8; j++) acc[i][j] = 0.f;

    for (int k0 = 0; k0 < K; k0 += BK) {
        #pragma unroll
        for (int r = 0; r < 2; r++) {
            float4 v = *(const float4*)&Ablk[(size_t)(aRow + r*64) * K + k0 + aCol];
            As[aCol + 0][aRow + r*64] = v.x;
            As[aCol + 1][aRow + r*64] = v.y;
            As[aCol + 2][aRow + r*64] = v.z;
            As[aCol + 3][aRow + r*64] = v.w;
        }
        #pragma unroll
        for (int r = 0; r < 2; r++) {
            float4 v = *(const float4*)&Bblk[(size_t)(k0 + bRow + r*8) * N + bCol];
            *(float4*)&Bs[bRow + r*8][bCol] = v;
        }
        __syncthreads();

        #pragma unroll
        for (int k = 0; k < BK; k++) {
            float ar[8], br[8];
            *(float4*)&ar[0] = *(float4*)&As[k][ty*8];
            *(float4*)&ar[4] = *(float4*)&As[k][ty*8 + 4];
            *(float4*)&br[0] = *(float4*)&Bs[k][tx*8];
            *(float4*)&br[4] = *(float4*)&Bs[k][tx*8 + 4];
            #pragma unroll
            for (int i = 0; i < 8; i++)
                #pragma unroll
                for (int j = 0; j < 8; j++)
                    acc[i][j] = fmaf(ar[i], br[j], acc[i][j]);
        }
        __syncthreads();
    }

    int rowBase = by*128 + ty*8;
    int colBase = bx*128 + tx*8;
    float bv[8];
    *(float4*)&bv[0] = *(const float4*)&bias[colBase];
    *(float4*)&bv[4] = *(const float4*)&bias[colBase + 4];
    #pragma unroll
    for (int i = 0; i < 8; i++) {
        float4 o0, o1;
        o0.x = acc[i][0] + bv[0]; o0.y = acc[i][1] + bv[1];
        o0.z = acc[i][2] + bv[2]; o0.w = acc[i][3] + bv[3];
        o1.x = acc[i][4] + bv[4]; o1.y = acc[i][5] + bv[5];
        o1.z = acc[i][6] + bv[6]; o1.w = acc[i][7] + bv[7];
        *(float4*)&C[(size_t)(rowBase + i) * N + colBase]     = o0;
        *(float4*)&C[(size_t)(rowBase + i) * N + colBase + 4] = o1;
    }
}

// ---------------------------------------------------------------------------
// Attention: one CTA per (b, h, query-block-of-64).
// Flash-style online softmax over 32-key tiles. Skipped blocks write zeros.
// Q/K/V stored as [B*S, DMODEL]; head h occupies cols h*64..h*64+63.
// ---------------------------------------------------------------------------
#define KT 32
__global__ __launch_bounds__(256) void attn_kernel(
    const float* __restrict__ Q, const float* __restrict__ K,
    const float* __restrict__ V, const int* __restrict__ keep,
    float* __restrict__ O)
{
    int blk = blockIdx.x;                 // 0 .. B*H*NB-1
    int qb = blk % NB;
    int h  = (blk / NB) % NHEAD;
    int b  = blk / (NB * NHEAD);
    int tid = threadIdx.x;

    const int row0 = b * SEQ + qb * BS;   // first query row (global)
    const int hoff = h * HD;

    if (!keep[b * NB + qb]) {
        // zero the 64x64 output tile
        for (int i = tid; i < BS * HD; i += 256) {
            int r = i >> 6, d = i & 63;
            O[(size_t)(row0 + r) * DMODEL + hoff + d] = 0.f;
        }
        return;
    }

    __shared__ float Qs[BS][HD + 1];      // 64 x 65
    __shared__ float KVs[KT][HD + 1];     // 32 x 65 (K then reused for V)
    __shared__ float Ss[BS][KT + 1];      // 64 x 33
    __shared__ float rm[BS], rl[BS], rc[BS];

    // load Q tile (64 x 64) via float4
    for (int i = tid; i < BS * HD / 4; i += 256) {
        int r = i >> 4, c4 = (i & 15) << 2;
        float4 v = *(const float4*)&Q[(size_t)(row0 + r) * DMODEL + hoff + c4];
        Qs[r][c4 + 0] = v.x; Qs[r][c4 + 1] = v.y;
        Qs[r][c4 + 2] = v.z; Qs[r][c4 + 3] = v.w;
    }
    if (tid < BS) { rm[tid] = -1e30f; rl[tid] = 0.f; }

    int tx = tid & 15, ty = tid >> 4;
    float acc[4][4];
    #pragma unroll
    for (int i = 0; i < 4; i++)
        #pragma unroll
        for (int j = 0; j < 4; j++) acc[i][j] = 0.f;

    __syncthreads();

    for (int kt = 0; kt < SEQ / KT; kt++) {
        // load K tile (32 x 64)
        for (int i = tid; i < KT * HD / 4; i += 256) {
            int r = i >> 4, c4 = (i & 15) << 2;
            float4 v = *(const float4*)&K[(size_t)(b * SEQ + kt * KT + r) * DMODEL + hoff + c4];
            KVs[r][c4 + 0] = v.x; KVs[r][c4 + 1] = v.y;
            KVs[r][c4 + 2] = v.z; KVs[r][c4 + 3] = v.w;
        }
        __syncthreads();

        // scores: thread computes rows 4*ty..+3, key-cols 2*tx..+1
        float s[4][2];
        #pragma unroll
        for (int i = 0; i < 4; i++) { s[i][0] = 0.f; s[i][1] = 0.f; }
        #pragma unroll 16
        for (int d = 0; d < HD; d++) {
            float qv0 = Qs[4*ty + 0][d];
            float qv1 = Qs[4*ty + 1][d];
            float qv2 = Qs[4*ty + 2][d];
            float qv3 = Qs[4*ty + 3][d];
            float kv0 = KVs[2*tx + 0][d];
            float kv1 = KVs[2*tx + 1][d];
            s[0][0] = fmaf(qv0, kv0, s[0][0]); s[0][1] = fmaf(qv0, kv1, s[0][1]);
            s[1][0] = fmaf(qv1, kv0, s[1][0]); s[1][1] = fmaf(qv1, kv1, s[1][1]);
            s[2][0] = fmaf(qv2, kv0, s[2][0]); s[2][1] = fmaf(qv2, kv1, s[2][1]);
            s[3][0] = fmaf(qv3, kv0, s[3][0]); s[3][1] = fmaf(qv3, kv1, s[3][1]);
        }
        #pragma unroll
        for (int i = 0; i < 4; i++) {
            Ss[4*ty + i][2*tx + 0] = s[i][0] * SCALE;
            Ss[4*ty + i][2*tx + 1] = s[i][1] * SCALE;
        }
        __syncthreads();

        // online softmax: one thread per query row
        if (tid < BS) {
            float m_old = rm[tid];
            float mx = m_old;
            #pragma unroll
            for (int k = 0; k < KT; k++) mx = fmaxf(mx, Ss[tid][k]);
            float c = __expf(m_old - mx);
            float sum = 0.f;
            #pragma unroll
            for (int k = 0; k < KT; k++) {
                float p = __expf(Ss[tid][k] - mx);
                Ss[tid][k] = p;
                sum += p;
            }
            rl[tid] = rl[tid] * c + sum;
            rm[tid] = mx;
            rc[tid] = c;
        }
        __syncthreads();

        // load V tile (reuses KVs), rescale accumulators
        for (int i = tid; i < KT * HD / 4; i += 256) {
            int r = i >> 4, c4 = (i & 15) << 2;
            float4 v = *(const float4*)&V[(size_t)(b * SEQ + kt * KT + r) * DMODEL + hoff + c4];
            KVs[r][c4 + 0] = v.x; KVs[r][c4 + 1] = v.y;
            KVs[r][c4 + 2] = v.z; KVs[r][c4 + 3] = v.w;
        }
        float cr[4];
        #pragma unroll
        for (int i = 0; i < 4; i++) cr[i] = rc[4*ty + i];
        #pragma unroll
        for (int i = 0; i < 4; i++)
            #pragma unroll
            for (int j = 0; j < 4; j++) acc[i][j] *= cr[i];
        __syncthreads();

        // O[4ty+i][4tx+j] += sum_k P[4ty+i][k] * V[k][4tx+j]
        #pragma unroll 8
        for (int k = 0; k < KT; k++) {
            float pv0 = Ss[4*ty + 0][k];
            float pv1 = Ss[4*ty + 1][k];
            float pv2 = Ss[4*ty + 2][k];
            float pv3 = Ss[4*ty + 3][k];
            float vv0 = KVs[k][4*tx + 0];
            float vv1 = KVs[k][4*tx + 1];
            float vv2 = KVs[k][4*tx + 2];
            float vv3 = KVs[k][4*tx + 3];
            acc[0][0] = fmaf(pv0, vv0, acc[0][0]); acc[0][1] = fmaf(pv0, vv1, acc[0][1]);
            acc[0][2] = fmaf(pv0, vv2, acc[0][2]); acc[0][3] = fmaf(pv0, vv3, acc[0][3]);
            acc[1][0] = fmaf(pv1, vv0, acc[1][0]); acc[1][1] = fmaf(pv1, vv1, acc[1][1]);
            acc[1][2] = fmaf(pv1, vv2, acc[1][2]); acc[1][3] = fmaf(pv1, vv3, acc[1][3]);
            acc[2][0] = fmaf(pv2, vv0, acc[2][0]); acc[2][1] = fmaf(pv2, vv1, acc[2][1]);
            acc[2][2] = fmaf(pv2, vv2, acc[2][2]); acc[2][3] = fmaf(pv2, vv3, acc[2][3]);
            acc[3][0] = fmaf(pv3, vv0, acc[3][0]); acc[3][1] = fmaf(pv3, vv1, acc[3][1]);
            acc[3][2] = fmaf(pv3, vv2, acc[3][2]); acc[3][3] = fmaf(pv3, vv3, acc[3][3]);
        }
        __syncthreads();
    }

    // epilogue: divide by row sums, store
    #pragma unroll
    for (int i = 0; i < 4; i++) {
        float inv = 1.0f / rl[4*ty + i];
        #pragma unroll
        for (int j = 0; j < 4; j++) {
            O[(size_t)(row0 + 4*ty + i) * DMODEL + hoff + 4*tx + j] = acc[i][j] * inv;
        }
    }
}

// ---------------------------------------------------------------------------
extern "C" void kernel_launch(void* const* d_in, const int* in_sizes, int n_in,
                              void* d_out, int out_size)
{
    const float* x  = (const float*)d_in[0];
    const float* G  = (const float*)d_in[1];
    const float* Wq = (const float*)d_in[2];
    const float* bq = (const float*)d_in[3];
    const float* Wk = (const float*)d_in[4];
    const float* bk = (const float*)d_in[5];
    const float* Wv = (const float*)d_in[6];
    const float* bv = (const float*)d_in[7];
    const float* Wo = (const float*)d_in[8];
    const float* bo = (const float*)d_in[9];
    float* out = (float*)d_out;

    float *q, *k, *v, *ao;
    int* keep;
    cudaGetSymbolAddress((void**)&q,  g_q);
    cudaGetSymbolAddress((void**)&k,  g_k);
    cudaGetSymbolAddress((void**)&v,  g_v);
    cudaGetSymbolAddress((void**)&ao, g_ao);
    cudaGetSymbolAddress((void**)&keep, g_keep);

    keep_kernel<<<BATCH * NB, 64>>>(G, keep);

    dim3 gemm_grid(DMODEL / 128, MTOT / 128);   // (8, 32)
    sgemm_bias_kernel<<<gemm_grid, 256>>>(x, Wq, bq, q, MTOT, DMODEL, DMODEL);
    sgemm_bias_kernel<<<gemm_grid, 256>>>(x, Wk, bk, k, MTOT, DMODEL, DMODEL);
    sgemm_bias_kernel<<<gemm_grid, 256>>>(x, Wv, bv, v, MTOT, DMODEL, DMODEL);

    attn_kernel<<<BATCH * NHEAD * NB, 256>>>(q, k, v, keep, ao);

    sgemm_bias_kernel<<<gemm_grid, 256>>>(ao, Wo, bo, out, MTOT, DMODEL, DMODEL);
}